// round 16
// baseline (speedup 1.0000x reference)
#include <cuda_runtime.h>
#include <cuda_fp16.h>
#include <cstdint>

#define BATCH 4
#define SEQ   2048
#define DIN   1024
#define DQ    1024
#define DV    1024

// Scratch (allocation-free rule: __device__ globals).
// g_q/g_k hold fp16 q,k. g_v holds fp16 V TRANSPOSED [B][DV][SEQ]. g_p fp32 scores.
__device__ float g_q[(size_t)BATCH * SEQ * DQ / 2];
__device__ float g_k[(size_t)BATCH * SEQ * DQ / 2];
__device__ float g_v[(size_t)BATCH * SEQ * DV / 2];
__device__ float g_p[(size_t)BATCH * SEQ * SEQ];
// g_r: fp16 converted inputs (28.3M halves) before scores; fp16 P (16.8M halves) after.
__device__ float g_r[(size_t)16 * 1024 * 1024];

#define RQ_OFF  ((size_t)0)
#define RK_OFF  ((size_t)BATCH * SEQ * DIN)
#define RV_OFF  ((size_t)2 * BATCH * SEQ * DIN)
#define RWQ_OFF ((size_t)3 * BATCH * SEQ * DIN)
#define RWK_OFF (RWQ_OFF + (size_t)DQ * DIN)
#define RWV_OFF (RWK_OFF + (size_t)DQ * DIN)

__device__ __forceinline__ void mma16(float* c, const uint32_t* a, const uint32_t* b) {
    asm volatile(
        "mma.sync.aligned.m16n8k16.row.col.f32.f16.f16.f32 "
        "{%0,%1,%2,%3}, {%4,%5,%6,%7}, {%8,%9}, {%0,%1,%2,%3};"
        : "+f"(c[0]), "+f"(c[1]), "+f"(c[2]), "+f"(c[3])
        : "r"(a[0]), "r"(a[1]), "r"(a[2]), "r"(a[3]), "r"(b[0]), "r"(b[1]));
}

__device__ __forceinline__ void cpa16(void* s, const void* g) {
    unsigned sa = (unsigned)__cvta_generic_to_shared(s);
    asm volatile("cp.async.cg.shared.global [%0], [%1], 16;" :: "r"(sa), "l"(g));
}
__device__ __forceinline__ void cpa_commit() { asm volatile("cp.async.commit_group;"); }
__device__ __forceinline__ void cpa_wait0()  { asm volatile("cp.async.wait_group 0;"); }
__device__ __forceinline__ void cpa_wait1()  { asm volatile("cp.async.wait_group 1;"); }
__device__ __forceinline__ void cpa_wait2()  { asm volatile("cp.async.wait_group 2;"); }

// ===========================================================================
// fp32 -> fp16 conversion pre-pass (4 floats / thread)
// ===========================================================================
__global__ void cvt_half_kernel(const float* __restrict__ in, __half* __restrict__ out)
{
    long i = ((long)blockIdx.x * 256 + threadIdx.x) * 4;
    float4 v = *(const float4*)(in + i);
    __half2 h0 = __floats2half2_rn(v.x, v.y);
    __half2 h1 = __floats2half2_rn(v.z, v.w);
    uint2 pk;
    pk.x = *(uint32_t*)&h0;
    pk.y = *(uint32_t*)&h1;
    *(uint2*)(out + i) = pk;
}

// ---------------------------------------------------------------------------
// GEMM NT (fp16 in, fp32 acc): C[m][n] = sum_k A[m][k]*B[n][k] (+ epilogue)
//   epi 0: Ch[row][col] = half(acc + bias[col])      (q,k projections)
//   epi 1: Cf = mask ? -1e9 : acc*scale              (scores, fp32)
//   epi 2: Vt[b][col][s] = half(acc + bias[col])     (V projection, transposed)
//   epi 3: Cf = acc                                  (PV output, fp32)
// CTA tile BM=128, BN=256, BK=32. 8 warps (2x4), warp tile 64x64, m16n8k16.
// Smem rows: 32 halves padded to 40 (word stride 20, conflict-free).
// Stage = A 5120 + B 10240 = 15360 halves = 30720 B; 4 stages = 122880 B.
// ---------------------------------------------------------------------------
#define NTH_STG 15360

__device__ __forceinline__ void nth_load(__half* sm, int st, int tid,
                                         const __half* Ab, const __half* Bb,
                                         int k0, int K)
{
    __half* sA = sm + (size_t)st * NTH_STG;
    __half* sB = sA + 5120;
#pragma unroll
    for (int i = 0; i < 6; i++) {
        int idx = i * 256 + tid;                 // 0..1535
        if (idx < 512) {                         // A: 128 rows x 4 chunks of 8 halves
            int r = idx >> 2, c = idx & 3;
            cpa16(sA + r * 40 + c * 8, Ab + (long)r * K + k0 + c * 8);
        } else {                                 // B: 256 rows x 4 chunks
            int j = idx - 512;
            int r = j >> 2, c = j & 3;
            cpa16(sB + r * 40 + c * 8, Bb + (long)r * K + k0 + c * 8);
        }
    }
    cpa_commit();
}

__global__ __launch_bounds__(256)
void gemm_nt_h(const __half* __restrict__ A, long sAz,
               const __half* __restrict__ B, long sBz,
               const float* __restrict__ bias,
               const int* __restrict__ mask, long sMz,
               float* __restrict__ Cf, __half* __restrict__ Ch, long sCz,
               int N, int K, float scale, int epi)
{
    extern __shared__ __half smh[];

    const int tid  = threadIdx.x;
    const int lane = tid & 31, warp = tid >> 5;
    const int wm = warp >> 2, wn = warp & 3;     // 2 x 4 warp grid
    const int gq = lane >> 2, tg = lane & 3;

    const __half* Ab = A + (long)blockIdx.z * sAz + (long)blockIdx.y * 128 * K;
    const __half* Bb = B + (long)blockIdx.z * sBz + (long)blockIdx.x * 256 * K;

    float acc[4][8][4];
#pragma unroll
    for (int i = 0; i < 4; i++)
#pragma unroll
        for (int j = 0; j < 8; j++)
#pragma unroll
            for (int l = 0; l < 4; l++) acc[i][j][l] = 0.f;

    const int NIT = K >> 5;

    nth_load(smh, 0, tid, Ab, Bb, 0, K);
    nth_load(smh, 1, tid, Ab, Bb, 32, K);
    nth_load(smh, 2, tid, Ab, Bb, 64, K);

    for (int it = 0; it < NIT; ++it) {
        if (it + 3 <= NIT - 1)      cpa_wait2();
        else if (it + 2 <= NIT - 1) cpa_wait1();
        else                        cpa_wait0();
        __syncthreads();
        if (it + 3 < NIT)
            nth_load(smh, (it + 3) & 3, tid, Ab, Bb, (it + 3) << 5, K);

        const uint32_t* wA = (const uint32_t*)(smh + (size_t)(it & 3) * NTH_STG);
        const uint32_t* wB = (const uint32_t*)(smh + (size_t)(it & 3) * NTH_STG + 5120);

#pragma unroll
        for (int ks = 0; ks < 2; ++ks) {         // two k16 steps per BK=32
            uint32_t af[4][4];
            uint32_t bf[8][2];
#pragma unroll
            for (int mt = 0; mt < 4; ++mt) {
                int r0 = wm * 64 + mt * 16 + gq;
                int w0 = r0 * 20 + ks * 8 + tg;
                af[mt][0] = wA[w0];
                af[mt][1] = wA[w0 + 160];        // +8 rows
                af[mt][2] = wA[w0 + 4];
                af[mt][3] = wA[w0 + 164];
            }
#pragma unroll
            for (int nt = 0; nt < 8; ++nt) {
                int rb = wn * 64 + nt * 8 + gq;
                int w0 = rb * 20 + ks * 8 + tg;
                bf[nt][0] = wB[w0];
                bf[nt][1] = wB[w0 + 4];
            }
#pragma unroll
            for (int mt = 0; mt < 4; ++mt)
#pragma unroll
                for (int nt = 0; nt < 8; ++nt)
                    mma16(acc[mt][nt], af[mt], bf[nt]);
        }
    }

    // epilogue
#pragma unroll
    for (int mt = 0; mt < 4; ++mt) {
        int row = blockIdx.y * 128 + wm * 64 + mt * 16 + gq;
#pragma unroll
        for (int nt = 0; nt < 8; ++nt) {
            int col = blockIdx.x * 256 + wn * 64 + nt * 8 + tg * 2;
            float* a = acc[mt][nt];
            if (epi == 0) {
                __half* C = Ch + (long)blockIdx.z * sCz;
                long r0 = (long)row * N + col, r1 = (long)(row + 8) * N + col;
                float b0 = bias[col], b1 = bias[col + 1];
                *(__half2*)(C + r0) = __floats2half2_rn(a[0] + b0, a[1] + b1);
                *(__half2*)(C + r1) = __floats2half2_rn(a[2] + b0, a[3] + b1);
            } else if (epi == 1) {
                float* C = Cf + (long)blockIdx.z * sCz;
                const int* M = mask + (long)blockIdx.z * sMz;
                long r0 = (long)row * N + col, r1 = (long)(row + 8) * N + col;
                C[r0]     = M[r0]     ? -1.0e9f : a[0] * scale;
                C[r0 + 1] = M[r0 + 1] ? -1.0e9f : a[1] * scale;
                C[r1]     = M[r1]     ? -1.0e9f : a[2] * scale;
                C[r1 + 1] = M[r1 + 1] ? -1.0e9f : a[3] * scale;
            } else if (epi == 2) {
                // V projection: write transposed Vt[b][col][s]
                long b = row >> 11, s = row & 2047;
                __half* T = Ch + b * ((long)DV * SEQ);
                float b0 = bias[col], b1 = bias[col + 1];
                T[(long)col * SEQ + s]           = __float2half(a[0] + b0);
                T[(long)(col + 1) * SEQ + s]     = __float2half(a[1] + b1);
                T[(long)col * SEQ + s + 8]       = __float2half(a[2] + b0);
                T[(long)(col + 1) * SEQ + s + 8] = __float2half(a[3] + b1);
            } else {
                float* C = Cf + (long)blockIdx.z * sCz;
                long r0 = (long)row * N + col, r1 = (long)(row + 8) * N + col;
                C[r0]     = a[0];
                C[r0 + 1] = a[1];
                C[r1]     = a[2];
                C[r1 + 1] = a[3];
            }
        }
    }
}

// ---------------------------------------------------------------------------
// Row softmax over fp32 scores P -> fp16 probabilities Ph.
// ---------------------------------------------------------------------------
__global__ void softmax_kernel(const float* __restrict__ P, __half* __restrict__ Ph)
{
    const float* p = P + (long)blockIdx.x * SEQ;
    __half* ph = Ph + (long)blockIdx.x * SEQ;
    const int tid = threadIdx.x;
    __shared__ float red[8];

    float v[8];
    float mx = -3.4e38f;
#pragma unroll
    for (int i = 0; i < 8; i++) {
        v[i] = p[tid + (i << 8)];
        mx = fmaxf(mx, v[i]);
    }
#pragma unroll
    for (int o = 16; o > 0; o >>= 1) mx = fmaxf(mx, __shfl_xor_sync(0xffffffffu, mx, o));
    if ((tid & 31) == 0) red[tid >> 5] = mx;
    __syncthreads();
    mx = red[0];
#pragma unroll
    for (int i = 1; i < 8; i++) mx = fmaxf(mx, red[i]);

    float sum = 0.f;
#pragma unroll
    for (int i = 0; i < 8; i++) {
        v[i] = expf(v[i] - mx);
        sum += v[i];
    }
#pragma unroll
    for (int o = 16; o > 0; o >>= 1) sum += __shfl_xor_sync(0xffffffffu, sum, o);
    __syncthreads();
    if ((tid & 31) == 0) red[tid >> 5] = sum;
    __syncthreads();
    float tot = 0.f;
#pragma unroll
    for (int i = 0; i < 8; i++) tot += red[i];
    float inv = 1.0f / tot;
#pragma unroll
    for (int i = 0; i < 8; i++)
        ph[tid + (i << 8)] = __float2half(v[i] * inv);
}

// ---------------------------------------------------------------------------
extern "C" void kernel_launch(void* const* d_in, const int* in_sizes, int n_in,
                              void* d_out, int out_size)
{
    const float* query = (const float*)d_in[0];
    const float* key   = (const float*)d_in[1];
    const float* value = (const float*)d_in[2];
    const int*   mask  = (const int*)d_in[3];     // bool stored as int32
    const float* Wq = (const float*)d_in[4];
    const float* bq = (const float*)d_in[5];
    const float* Wk = (const float*)d_in[6];
    const float* bk = (const float*)d_in[7];
    const float* Wv = (const float*)d_in[8];
    const float* bv = (const float*)d_in[9];
    float* out = (float*)d_out;

    void *qb, *kb, *vb, *pb, *rb;
    cudaGetSymbolAddress(&qb, g_q);
    cudaGetSymbolAddress(&kb, g_k);
    cudaGetSymbolAddress(&vb, g_v);
    cudaGetSymbolAddress(&pb, g_p);
    cudaGetSymbolAddress(&rb, g_r);
    __half* qh = (__half*)qb;
    __half* kh = (__half*)kb;
    __half* vh = (__half*)vb;      // transposed [B][DV][SEQ]
    float*  pf = (float*)pb;
    __half* rh = (__half*)rb;

    const int SMEM_NT = 4 * NTH_STG * 2;   // 122880 B
    cudaFuncSetAttribute(gemm_nt_h, cudaFuncAttributeMaxDynamicSharedMemorySize, SMEM_NT);

    // fp32 -> fp16 conversion of all projection inputs (scratch in g_r)
    const long NACT = (long)BATCH * SEQ * DIN;   // 8388608
    cvt_half_kernel<<<NACT / 1024, 256>>>(query, rh + RQ_OFF);
    cvt_half_kernel<<<NACT / 1024, 256>>>(key,   rh + RK_OFF);
    cvt_half_kernel<<<NACT / 1024, 256>>>(value, rh + RV_OFF);
    cvt_half_kernel<<<(DQ * DIN) / 1024, 256>>>(Wq, rh + RWQ_OFF);
    cvt_half_kernel<<<(DQ * DIN) / 1024, 256>>>(Wk, rh + RWK_OFF);
    cvt_half_kernel<<<(DV * DIN) / 1024, 256>>>(Wv, rh + RWV_OFF);

    dim3 blk(256);

    // QKV projections: M = B*S = 8192, N = 1024, K = 1024
    dim3 gp(DQ / 256, (BATCH * SEQ) / 128, 1);
    gemm_nt_h<<<gp, blk, SMEM_NT>>>(rh + RQ_OFF, 0, rh + RWQ_OFF, 0, bq,
                                    nullptr, 0, nullptr, qh, 0, DQ, DIN, 0.f, 0);
    gemm_nt_h<<<gp, blk, SMEM_NT>>>(rh + RK_OFF, 0, rh + RWK_OFF, 0, bk,
                                    nullptr, 0, nullptr, kh, 0, DQ, DIN, 0.f, 0);
    gemm_nt_h<<<gp, blk, SMEM_NT>>>(rh + RV_OFF, 0, rh + RWV_OFF, 0, bv,
                                    nullptr, 0, nullptr, vh, 0, DV, DIN, 0.f, 2);

    // scores: per batch M = N = SEQ, K = DQ, scale = 1/sqrt(1024) -> fp32 P
    dim3 gs(SEQ / 256, SEQ / 128, BATCH);
    gemm_nt_h<<<gs, blk, SMEM_NT>>>(qh, (long)SEQ * DQ, kh, (long)SEQ * DQ,
                                    nullptr, mask, (long)SEQ * SEQ,
                                    pf, nullptr, (long)SEQ * SEQ, SEQ, DQ, 0.03125f, 1);

    // softmax over rows: fp32 scores -> fp16 probabilities (reuse g_r)
    softmax_kernel<<<BATCH * SEQ, 256>>>(pf, rh);

    // out = P @ Vt : per batch M = SEQ, N = DV, K = SEQ (NT with transposed V)
    dim3 ga(DV / 256, SEQ / 128, BATCH);
    gemm_nt_h<<<ga, blk, SMEM_NT>>>(rh, (long)SEQ * SEQ, vh, (long)DV * SEQ,
                                    nullptr, nullptr, 0,
                                    out, nullptr, (long)SEQ * DV, DV, SEQ, 0.f, 3);
}

// round 17
// speedup vs baseline: 1.0640x; 1.0640x over previous
#include <cuda_runtime.h>
#include <cuda_fp16.h>
#include <cstdint>

#define BATCH 4
#define SEQ   2048
#define DIN   1024
#define DQ    1024
#define DV    1024

// Scratch (allocation-free rule: __device__ globals).
__device__ float g_q[(size_t)BATCH * SEQ * DQ / 2];   // fp16 q
__device__ float g_k[(size_t)BATCH * SEQ * DQ / 2];   // fp16 k
__device__ float g_v[(size_t)BATCH * SEQ * DV / 2];   // fp16 v (normal [B][S][DV])
__device__ float g_p[(size_t)BATCH * SEQ * SEQ];      // fp32 scores
// g_r (32M halves): fp16 inputs (28.3M) during projections; then
// P fp16 [0,16.8M) + Vt fp16 [16.8M, 25.2M).
__device__ float g_r[(size_t)16 * 1024 * 1024];

#define RQ_OFF  ((size_t)0)
#define RK_OFF  ((size_t)BATCH * SEQ * DIN)
#define RV_OFF  ((size_t)2 * BATCH * SEQ * DIN)
#define RWQ_OFF ((size_t)3 * BATCH * SEQ * DIN)
#define RWK_OFF (RWQ_OFF + (size_t)DQ * DIN)
#define RWV_OFF (RWK_OFF + (size_t)DQ * DIN)
#define VT_OFF  ((size_t)BATCH * SEQ * SEQ)           // 16777216 halves

__device__ __forceinline__ void mma16(float* c, const uint32_t* a, const uint32_t* b) {
    asm volatile(
        "mma.sync.aligned.m16n8k16.row.col.f32.f16.f16.f32 "
        "{%0,%1,%2,%3}, {%4,%5,%6,%7}, {%8,%9}, {%0,%1,%2,%3};"
        : "+f"(c[0]), "+f"(c[1]), "+f"(c[2]), "+f"(c[3])
        : "r"(a[0]), "r"(a[1]), "r"(a[2]), "r"(a[3]), "r"(b[0]), "r"(b[1]));
}

__device__ __forceinline__ void cpa16(void* s, const void* g) {
    unsigned sa = (unsigned)__cvta_generic_to_shared(s);
    asm volatile("cp.async.cg.shared.global [%0], [%1], 16;" :: "r"(sa), "l"(g));
}
__device__ __forceinline__ void cpa_commit() { asm volatile("cp.async.commit_group;"); }
__device__ __forceinline__ void cpa_wait0()  { asm volatile("cp.async.wait_group 0;"); }
__device__ __forceinline__ void cpa_wait1()  { asm volatile("cp.async.wait_group 1;"); }

// ===========================================================================
// fp32 -> fp16 conversion pre-pass (4 floats / thread)
// ===========================================================================
__global__ void cvt_half_kernel(const float* __restrict__ in, __half* __restrict__ out)
{
    long i = ((long)blockIdx.x * 256 + threadIdx.x) * 4;
    float4 v = *(const float4*)(in + i);
    __half2 h0 = __floats2half2_rn(v.x, v.y);
    __half2 h1 = __floats2half2_rn(v.z, v.w);
    uint2 pk;
    pk.x = *(uint32_t*)&h0;
    pk.y = *(uint32_t*)&h1;
    *(uint2*)(out + i) = pk;
}

// ===========================================================================
// fp16 tiled transpose: in [B][SEQ][DV] -> out [B][DV][SEQ]. 64x64 tiles.
// ===========================================================================
__global__ void transpose_h(const __half* __restrict__ in, __half* __restrict__ out)
{
    __shared__ __half t[64][68];                 // 68 pad: 8B-aligned rows
    const int d0 = blockIdx.x * 64, s0 = blockIdx.y * 64;
    const __half* I = in + (long)blockIdx.z * SEQ * DV;
    __half* O = out + (long)blockIdx.z * DV * SEQ;
    const int tid = threadIdx.x;
#pragma unroll
    for (int i = 0; i < 4; i++) {
        int idx = i * 256 + tid;                 // 1024 x 4 halves
        int r = idx >> 4, c = (idx & 15) << 2;
        *(uint2*)&t[r][c] = *(const uint2*)&I[(long)(s0 + r) * DV + d0 + c];
    }
    __syncthreads();
#pragma unroll
    for (int i = 0; i < 4; i++) {
        int idx = i * 256 + tid;
        int r = idx >> 4, c = (idx & 15) << 2;   // r = d-local, c = s-local chunk
        __half2 h0 = __halves2half2(t[c][r], t[c + 1][r]);
        __half2 h1 = __halves2half2(t[c + 2][r], t[c + 3][r]);
        uint2 pk;
        pk.x = *(uint32_t*)&h0;
        pk.y = *(uint32_t*)&h1;
        *(uint2*)&O[(long)(d0 + r) * SEQ + s0 + c] = pk;
    }
}

// ---------------------------------------------------------------------------
// GEMM NT (fp16 in, fp32 acc): C[m][n] = sum_k A[m][k]*B[n][k] (+ epilogue)
//   epi 0: Ch = half(acc + bias[n])       (projections -> fp16)
//   epi 1: Cf = mask ? -1e9 : acc*scale   (scores -> fp32)
//   epi 3: Cf = acc                       (PV output -> fp32)
// Tiles BM=BN=128, BK=32. 8 warps (2x4), warp tile 64x32, m16n8k16.
// Smem rows: 32 data halves padded to 40 (word-stride 20 -> conflict-free).
// Stage = 10240 halves = 20480 B; 3 stages. 2 CTAs/SM.
// ---------------------------------------------------------------------------
#define NTH_STG 10240

__device__ __forceinline__ void nth_load(__half* sm, int st, int tid,
                                         const __half* Ab, const __half* Bb,
                                         int k0, int K)
{
    __half* sA = sm + (size_t)st * NTH_STG;
    __half* sB = sA + 5120;
#pragma unroll
    for (int i = 0; i < 4; i++) {
        int idx = i * 256 + tid;                 // 0..1023
        int r = (idx & 511) >> 2, c = idx & 3;   // row, 16B-chunk (8 halves)
        if (idx < 512)
            cpa16(sA + r * 40 + c * 8, Ab + (long)r * K + k0 + c * 8);
        else
            cpa16(sB + r * 40 + c * 8, Bb + (long)r * K + k0 + c * 8);
    }
    cpa_commit();
}

__global__ __launch_bounds__(256, 2)
void gemm_nt_h(const __half* __restrict__ A, long sAz,
               const __half* __restrict__ B, long sBz,
               const float* __restrict__ bias,
               const int* __restrict__ mask, long sMz,
               float* __restrict__ Cf, __half* __restrict__ Ch, long sCz,
               int N, int K, float scale, int epi)
{
    extern __shared__ __half smh[];

    const int tid  = threadIdx.x;
    const int lane = tid & 31, warp = tid >> 5;
    const int wm = warp >> 2, wn = warp & 3;     // 2 x 4 warp grid
    const int gq = lane >> 2, tg = lane & 3;

    const __half* Ab = A + (long)blockIdx.z * sAz + (long)blockIdx.y * 128 * K;
    const __half* Bb = B + (long)blockIdx.z * sBz + (long)blockIdx.x * 128 * K;

    float acc[4][4][4];
#pragma unroll
    for (int i = 0; i < 4; i++)
#pragma unroll
        for (int j = 0; j < 4; j++)
#pragma unroll
            for (int l = 0; l < 4; l++) acc[i][j][l] = 0.f;

    const int NIT = K >> 5;

    nth_load(smh, 0, tid, Ab, Bb, 0, K);
    nth_load(smh, 1, tid, Ab, Bb, 32, K);

    int st = 0, ld = 2;
    for (int it = 0; it < NIT; ++it) {
        if (it + 1 < NIT) cpa_wait1(); else cpa_wait0();
        __syncthreads();
        if (it + 2 < NIT) {
            nth_load(smh, ld, tid, Ab, Bb, (it + 2) << 5, K);
            if (++ld == 3) ld = 0;
        }

        const uint32_t* wA = (const uint32_t*)(smh + (size_t)st * NTH_STG);
        const uint32_t* wB = (const uint32_t*)(smh + (size_t)st * NTH_STG + 5120);
        if (++st == 3) st = 0;

#pragma unroll
        for (int ks = 0; ks < 2; ++ks) {         // two k16 steps per BK=32
            uint32_t af[4][4];
            uint32_t bf[4][2];
#pragma unroll
            for (int mt = 0; mt < 4; ++mt) {
                int r0 = wm * 64 + mt * 16 + gq;
                int w0 = r0 * 20 + ks * 8 + tg;
                af[mt][0] = wA[w0];
                af[mt][1] = wA[w0 + 160];        // +8 rows
                af[mt][2] = wA[w0 + 4];
                af[mt][3] = wA[w0 + 164];
            }
#pragma unroll
            for (int nt = 0; nt < 4; ++nt) {
                int rb = wn * 32 + nt * 8 + gq;
                int w0 = rb * 20 + ks * 8 + tg;
                bf[nt][0] = wB[w0];
                bf[nt][1] = wB[w0 + 4];
            }
#pragma unroll
            for (int mt = 0; mt < 4; ++mt)
#pragma unroll
                for (int nt = 0; nt < 4; ++nt)
                    mma16(acc[mt][nt], af[mt], bf[nt]);
        }
    }

    // epilogue
#pragma unroll
    for (int mt = 0; mt < 4; ++mt) {
        int row = blockIdx.y * 128 + wm * 64 + mt * 16 + gq;
#pragma unroll
        for (int nt = 0; nt < 4; ++nt) {
            int col = blockIdx.x * 128 + wn * 32 + nt * 8 + tg * 2;
            float* a = acc[mt][nt];
            long r0 = (long)row * N + col, r1 = (long)(row + 8) * N + col;
            if (epi == 0) {
                __half* C = Ch + (long)blockIdx.z * sCz;
                float b0 = bias[col], b1 = bias[col + 1];
                *(__half2*)(C + r0) = __floats2half2_rn(a[0] + b0, a[1] + b1);
                *(__half2*)(C + r1) = __floats2half2_rn(a[2] + b0, a[3] + b1);
            } else if (epi == 1) {
                float* C = Cf + (long)blockIdx.z * sCz;
                const int* M = mask + (long)blockIdx.z * sMz;
                C[r0]     = M[r0]     ? -1.0e9f : a[0] * scale;
                C[r0 + 1] = M[r0 + 1] ? -1.0e9f : a[1] * scale;
                C[r1]     = M[r1]     ? -1.0e9f : a[2] * scale;
                C[r1 + 1] = M[r1 + 1] ? -1.0e9f : a[3] * scale;
            } else {
                float* C = Cf + (long)blockIdx.z * sCz;
                C[r0]     = a[0];
                C[r0 + 1] = a[1];
                C[r1]     = a[2];
                C[r1 + 1] = a[3];
            }
        }
    }
}

// ---------------------------------------------------------------------------
// Row softmax over fp32 scores P -> fp16 probabilities Ph. float4 I/O, __expf.
// ---------------------------------------------------------------------------
__global__ void softmax_kernel(const float* __restrict__ P, __half* __restrict__ Ph)
{
    const float* p = P + (long)blockIdx.x * SEQ;
    __half* ph = Ph + (long)blockIdx.x * SEQ;
    const int tid = threadIdx.x;
    __shared__ float red[8];

    float4 va = *(const float4*)(p + (tid << 2));
    float4 vb = *(const float4*)(p + 1024 + (tid << 2));

    float mx = fmaxf(fmaxf(fmaxf(va.x, va.y), fmaxf(va.z, va.w)),
                     fmaxf(fmaxf(vb.x, vb.y), fmaxf(vb.z, vb.w)));
#pragma unroll
    for (int o = 16; o > 0; o >>= 1) mx = fmaxf(mx, __shfl_xor_sync(0xffffffffu, mx, o));
    if ((tid & 31) == 0) red[tid >> 5] = mx;
    __syncthreads();
    mx = red[0];
#pragma unroll
    for (int i = 1; i < 8; i++) mx = fmaxf(mx, red[i]);

    va.x = __expf(va.x - mx); va.y = __expf(va.y - mx);
    va.z = __expf(va.z - mx); va.w = __expf(va.w - mx);
    vb.x = __expf(vb.x - mx); vb.y = __expf(vb.y - mx);
    vb.z = __expf(vb.z - mx); vb.w = __expf(vb.w - mx);
    float sum = (va.x + va.y) + (va.z + va.w) + (vb.x + vb.y) + (vb.z + vb.w);
#pragma unroll
    for (int o = 16; o > 0; o >>= 1) sum += __shfl_xor_sync(0xffffffffu, sum, o);
    __syncthreads();
    if ((tid & 31) == 0) red[tid >> 5] = sum;
    __syncthreads();
    float tot = 0.f;
#pragma unroll
    for (int i = 0; i < 8; i++) tot += red[i];
    float inv = 1.0f / tot;

    __half2 h0 = __floats2half2_rn(va.x * inv, va.y * inv);
    __half2 h1 = __floats2half2_rn(va.z * inv, va.w * inv);
    uint2 pk;
    pk.x = *(uint32_t*)&h0; pk.y = *(uint32_t*)&h1;
    *(uint2*)(ph + (tid << 2)) = pk;
    h0 = __floats2half2_rn(vb.x * inv, vb.y * inv);
    h1 = __floats2half2_rn(vb.z * inv, vb.w * inv);
    pk.x = *(uint32_t*)&h0; pk.y = *(uint32_t*)&h1;
    *(uint2*)(ph + 1024 + (tid << 2)) = pk;
}

// ---------------------------------------------------------------------------
extern "C" void kernel_launch(void* const* d_in, const int* in_sizes, int n_in,
                              void* d_out, int out_size)
{
    const float* query = (const float*)d_in[0];
    const float* key   = (const float*)d_in[1];
    const float* value = (const float*)d_in[2];
    const int*   mask  = (const int*)d_in[3];     // bool stored as int32
    const float* Wq = (const float*)d_in[4];
    const float* bq = (const float*)d_in[5];
    const float* Wk = (const float*)d_in[6];
    const float* bk = (const float*)d_in[7];
    const float* Wv = (const float*)d_in[8];
    const float* bv = (const float*)d_in[9];
    float* out = (float*)d_out;

    void *qb, *kb, *vb, *pb, *rb;
    cudaGetSymbolAddress(&qb, g_q);
    cudaGetSymbolAddress(&kb, g_k);
    cudaGetSymbolAddress(&vb, g_v);
    cudaGetSymbolAddress(&pb, g_p);
    cudaGetSymbolAddress(&rb, g_r);
    __half* qh = (__half*)qb;
    __half* kh = (__half*)kb;
    __half* vh = (__half*)vb;
    float*  pf = (float*)pb;
    __half* rh = (__half*)rb;

    const int SMEM_NT = 3 * NTH_STG * 2;   // 61440 B
    cudaFuncSetAttribute(gemm_nt_h, cudaFuncAttributeMaxDynamicSharedMemorySize, SMEM_NT);

    // fp32 -> fp16 conversion of all projection inputs (scratch in g_r)
    const long NACT = (long)BATCH * SEQ * DIN;   // 8388608
    cvt_half_kernel<<<NACT / 1024, 256>>>(query, rh + RQ_OFF);
    cvt_half_kernel<<<NACT / 1024, 256>>>(key,   rh + RK_OFF);
    cvt_half_kernel<<<NACT / 1024, 256>>>(value, rh + RV_OFF);
    cvt_half_kernel<<<(DQ * DIN) / 1024, 256>>>(Wq, rh + RWQ_OFF);
    cvt_half_kernel<<<(DQ * DIN) / 1024, 256>>>(Wk, rh + RWK_OFF);
    cvt_half_kernel<<<(DV * DIN) / 1024, 256>>>(Wv, rh + RWV_OFF);

    dim3 blk(256);

    // QKV projections: M = B*S = 8192, N = 1024, K = 1024 -> fp16 outputs
    dim3 gp(DQ / 128, (BATCH * SEQ) / 128, 1);
    gemm_nt_h<<<gp, blk, SMEM_NT>>>(rh + RQ_OFF, 0, rh + RWQ_OFF, 0, bq,
                                    nullptr, 0, nullptr, qh, 0, DQ, DIN, 0.f, 0);
    gemm_nt_h<<<gp, blk, SMEM_NT>>>(rh + RK_OFF, 0, rh + RWK_OFF, 0, bk,
                                    nullptr, 0, nullptr, kh, 0, DQ, DIN, 0.f, 0);
    gemm_nt_h<<<gp, blk, SMEM_NT>>>(rh + RV_OFF, 0, rh + RWV_OFF, 0, bv,
                                    nullptr, 0, nullptr, vh, 0, DV, DIN, 0.f, 0);

    // transpose V: [B][S][DV] -> Vt [B][DV][S]  (into g_r after V-input region)
    {
        dim3 gt(DV / 64, SEQ / 64, BATCH);
        transpose_h<<<gt, blk>>>(vh, rh + VT_OFF);
    }

    // scores: per batch M = N = SEQ, K = DQ, scale = 1/sqrt(1024) -> fp32 P
    dim3 gs(SEQ / 128, SEQ / 128, BATCH);
    gemm_nt_h<<<gs, blk, SMEM_NT>>>(qh, (long)SEQ * DQ, kh, (long)SEQ * DQ,
                                    nullptr, mask, (long)SEQ * SEQ,
                                    pf, nullptr, (long)SEQ * SEQ, SEQ, DQ, 0.03125f, 1);

    // softmax over rows: fp32 scores -> fp16 probabilities (g_r[0..16.8M))
    softmax_kernel<<<BATCH * SEQ, 256>>>(pf, rh);

    // out = P @ Vt : per batch M = SEQ, N = DV, K = SEQ (NT, fp32 out)
    dim3 ga(DV / 128, SEQ / 128, BATCH);
    gemm_nt_h<<<ga, blk, SMEM_NT>>>(rh, (long)SEQ * SEQ, rh + VT_OFF, (long)DV * SEQ,
                                    nullptr, nullptr, 0,
                                    out, nullptr, (long)SEQ * DV, DV, SEQ, 0.f, 3);
}